// round 8
// baseline (speedup 1.0000x reference)
#include <cuda_runtime.h>

// ---------------------------------------------------------------------------
// BatchedGeometryComputation
//   out = [centroids (n_blocks*3) | rel (n_atoms*3) | dist (n_atoms) | rbf (n_atoms*16)]
// block_id is SORTED ascending.
// ---------------------------------------------------------------------------

#define RBF_DIM 16
#define MAX_BLOCKS_SCRATCH 262144
#define TPB 256
#define PERSIST_GRID 1184   // ~148 SMs * 8 blocks; grid-stride handles mismatch

// scratch: per-block (sum_x, sum_y, sum_z, count)
__device__ float4 g_sums[MAX_BLOCKS_SCRATCH];

__global__ void k_zero_sums(int n_blocks) {
    for (int i = blockIdx.x * blockDim.x + threadIdx.x; i < n_blocks;
         i += gridDim.x * blockDim.x)
        g_sums[i] = make_float4(0.f, 0.f, 0.f, 0.f);
}

// Persistent. One atom per lane per tile; pos staged via float4 into shared;
// warp-level segmented reduction over sorted ids; heads issue atomics.
__global__ void __launch_bounds__(TPB)
k_accum(const float* __restrict__ pos,
        const int* __restrict__ bid,
        int n_atoms) {
    __shared__ float s_p[3 * TPB];
    int t    = threadIdx.x;
    int lane = t & 31;
    int ntiles = (n_atoms + TPB - 1) / TPB;

    for (int tile = blockIdx.x; tile < ntiles; tile += gridDim.x) {
        int a0 = tile * TPB;
        bool fullt = (a0 + TPB) <= n_atoms;

        __syncthreads();   // protect s_p from previous iteration's readers
        if (fullt) {
            const float4* p4 = (const float4*)(pos + (size_t)3 * a0);
            if (t < (3 * TPB / 4)) ((float4*)s_p)[t] = p4[t];
        } else {
            for (int k = t; k < 3 * TPB; k += TPB) {
                int gi = 3 * a0 + k;
                s_p[k] = (gi < 3 * n_atoms) ? pos[gi] : 0.f;
            }
        }
        __syncthreads();

        int i = a0 + t;
        bool valid = i < n_atoms;
        int idx = valid ? i : (n_atoms - 1);

        int   b   = bid[idx];
        float sx  = valid ? s_p[3 * t + 0] : 0.f;
        float sy  = valid ? s_p[3 * t + 1] : 0.f;
        float sz  = valid ? s_p[3 * t + 2] : 0.f;
        float cnt = valid ? 1.f : 0.f;

#pragma unroll
        for (int off = 1; off < 32; off <<= 1) {
            int   ob = __shfl_down_sync(0xffffffffu, b, off);
            float ox = __shfl_down_sync(0xffffffffu, sx, off);
            float oy = __shfl_down_sync(0xffffffffu, sy, off);
            float oz = __shfl_down_sync(0xffffffffu, sz, off);
            float oc = __shfl_down_sync(0xffffffffu, cnt, off);
            if (lane + off < 32 && ob == b) {
                sx += ox; sy += oy; sz += oz; cnt += oc;
            }
        }

        int prev_b = __shfl_up_sync(0xffffffffu, b, 1);
        bool head = (lane == 0) || (prev_b != b);
        if (head && cnt > 0.f) {
            float* p = (float*)&g_sums[b];
            atomicAdd(p + 0, sx);
            atomicAdd(p + 1, sy);
            atomicAdd(p + 2, sz);
            atomicAdd(p + 3, cnt);
        }
    }
}

__global__ void k_centroid(float* __restrict__ out_c, int n_blocks) {
    for (int i = blockIdx.x * blockDim.x + threadIdx.x; i < n_blocks;
         i += gridDim.x * blockDim.x) {
        float4 s = g_sums[i];
        float inv = 1.f / fmaxf(s.w, 1.f);
        out_c[3 * i + 0] = s.x * inv;
        out_c[3 * i + 1] = s.y * inv;
        out_c[3 * i + 2] = s.z * inv;
    }
}

// Persistent. Per tile: float4-staged pos, one atom/thread compute, rel
// written back to shared and stored cooperatively as float4, rbf as 4x
// STG.128 streaming stores. Centers/widths staged once per CTA.
__global__ void __launch_bounds__(TPB)
k_atoms(const float* __restrict__ pos,
        const int* __restrict__ bid,
        const float* __restrict__ centers,
        const float* __restrict__ widths,
        float* __restrict__ out_rel,
        float* __restrict__ out_dist,
        float4* __restrict__ out_rbf,     // n_atoms * 4 float4
        int n_atoms) {
    __shared__ float s_c[RBF_DIM];
    __shared__ float s_iw[RBF_DIM];
    __shared__ float s_xyz[3 * TPB];      // staged pos, then reused for rel

    int t = threadIdx.x;
    if (t < RBF_DIM) {
        s_c[t] = centers[t];
        float w = widths[t];
        s_iw[t] = 1.f / (2.f * w * w);
    }

    int ntiles = (n_atoms + TPB - 1) / TPB;

    for (int tile = blockIdx.x; tile < ntiles; tile += gridDim.x) {
        int a0 = tile * TPB;
        bool fullt = (a0 + TPB) <= n_atoms;

        __syncthreads();   // protect s_xyz from previous iteration's coop store
        if (fullt) {
            const float4* p4 = (const float4*)(pos + (size_t)3 * a0);
            if (t < (3 * TPB / 4)) ((float4*)s_xyz)[t] = p4[t];
        } else {
            for (int k = t; k < 3 * TPB; k += TPB) {
                int gi = 3 * a0 + k;
                s_xyz[k] = (gi < 3 * n_atoms) ? pos[gi] : 0.f;
            }
        }
        __syncthreads();

        int i = a0 + t;
        bool act = i < n_atoms;
        float d = 0.f;

        if (act) {
            int b = bid[i];
            float4 s = g_sums[b];             // single LDG.128, broadcast-friendly
            float inv = 1.f / fmaxf(s.w, 1.f);

            float rx = s_xyz[3 * t + 0] - s.x * inv;
            float ry = s_xyz[3 * t + 1] - s.y * inv;
            float rz = s_xyz[3 * t + 2] - s.z * inv;

            s_xyz[3 * t + 0] = rx;            // self-overwrite, no hazard
            s_xyz[3 * t + 1] = ry;
            s_xyz[3 * t + 2] = rz;

            d = sqrtf(rx * rx + ry * ry + rz * rz);
            __stcs(&out_dist[i], d);
        }
        __syncthreads();

        if (fullt) {
            float4* r4 = (float4*)(out_rel + (size_t)3 * a0);
            if (t < (3 * TPB / 4)) __stcs(&r4[t], ((const float4*)s_xyz)[t]);
        } else {
            for (int k = t; k < 3 * TPB; k += TPB) {
                int gi = 3 * a0 + k;
                if (gi < 3 * n_atoms) out_rel[gi] = s_xyz[k];
            }
        }

        if (act) {
            size_t rb = (size_t)i * (RBF_DIM / 4);
            {
                float4 v0, v1;
                float u;
                u = d - s_c[0]; v0.x = __expf(-u * u * s_iw[0]);
                u = d - s_c[1]; v0.y = __expf(-u * u * s_iw[1]);
                u = d - s_c[2]; v0.z = __expf(-u * u * s_iw[2]);
                u = d - s_c[3]; v0.w = __expf(-u * u * s_iw[3]);
                u = d - s_c[4]; v1.x = __expf(-u * u * s_iw[4]);
                u = d - s_c[5]; v1.y = __expf(-u * u * s_iw[5]);
                u = d - s_c[6]; v1.z = __expf(-u * u * s_iw[6]);
                u = d - s_c[7]; v1.w = __expf(-u * u * s_iw[7]);
                __stcs(&out_rbf[rb + 0], v0);
                __stcs(&out_rbf[rb + 1], v1);
            }
            {
                float4 v0, v1;
                float u;
                u = d - s_c[8];  v0.x = __expf(-u * u * s_iw[8]);
                u = d - s_c[9];  v0.y = __expf(-u * u * s_iw[9]);
                u = d - s_c[10]; v0.z = __expf(-u * u * s_iw[10]);
                u = d - s_c[11]; v0.w = __expf(-u * u * s_iw[11]);
                u = d - s_c[12]; v1.x = __expf(-u * u * s_iw[12]);
                u = d - s_c[13]; v1.y = __expf(-u * u * s_iw[13]);
                u = d - s_c[14]; v1.z = __expf(-u * u * s_iw[14]);
                u = d - s_c[15]; v1.w = __expf(-u * u * s_iw[15]);
                __stcs(&out_rbf[rb + 2], v0);
                __stcs(&out_rbf[rb + 3], v1);
            }
        }
    }
}

static inline int clamp_grid(long long b) {
    if (b < 1) return 1;
    if (b > 1048576) return 1048576;
    return (int)b;
}

extern "C" void kernel_launch(void* const* d_in, const int* in_sizes, int n_in,
                              void* d_out, int out_size) {
    const float* pos     = (const float*)d_in[0];  // [n_atoms*3]
    const int*   bid     = (const int*)d_in[1];    // [n_atoms]
    // d_in[2] = n_blocks scalar on device; derive arithmetically (no sync copies)
    const float* centers = (const float*)d_in[3];  // [16]
    const float* widths  = (const float*)d_in[4];  // [16]

    int n_atoms  = in_sizes[0] / 3;
    long long nb = ((long long)out_size - (long long)n_atoms * (3 + 1 + RBF_DIM)) / 3;
    int n_blocks = (int)nb;
    if (n_blocks < 1) n_blocks = 1;
    if (n_blocks > MAX_BLOCKS_SCRATCH) n_blocks = MAX_BLOCKS_SCRATCH;

    float* out      = (float*)d_out;
    float* out_cent = out;                                    // n_blocks*3
    float* out_rel  = out + (size_t)n_blocks * 3;             // n_atoms*3
    float* out_dist = out_rel + (size_t)n_atoms * 3;          // n_atoms
    float4* out_rbf = (float4*)(out_dist + (size_t)n_atoms);  // n_atoms*16 floats

    long long ntiles = ((long long)n_atoms + TPB - 1) / TPB;
    int pg = (int)(ntiles < PERSIST_GRID ? (ntiles < 1 ? 1 : ntiles) : PERSIST_GRID);

    // 1) zero scratch
    k_zero_sums<<<clamp_grid((n_blocks + 255) / 256), 256>>>(n_blocks);

    // 2) segment sums (persistent, staged, warp-aggregated atomics)
    if (n_atoms > 0)
        k_accum<<<pg, TPB>>>(pos, bid, n_atoms);

    // 3) centroids output
    k_centroid<<<clamp_grid((n_blocks + 255) / 256), 256>>>(out_cent, n_blocks);

    // 4) per-atom rel/dist/rbf (persistent; reads g_sums directly)
    if (n_atoms > 0)
        k_atoms<<<pg, TPB>>>(pos, bid, centers, widths,
                             out_rel, out_dist, out_rbf, n_atoms);
}

// round 9
// speedup vs baseline: 1.3696x; 1.3696x over previous
#include <cuda_runtime.h>

// ---------------------------------------------------------------------------
// BatchedGeometryComputation
//   out = [centroids (n_blocks*3) | rel (n_atoms*3) | dist (n_atoms) | rbf (n_atoms*16)]
// block_id is SORTED ascending.
// ---------------------------------------------------------------------------

#define RBF_DIM 16
#define MAX_BLOCKS_SCRATCH 262144
#define TPB 256

// scratch: per-block (sum_x, sum_y, sum_z, count)
__device__ float4 g_sums[MAX_BLOCKS_SCRATCH];

__global__ void k_zero_sums(int n_blocks) {
    for (int i = blockIdx.x * blockDim.x + threadIdx.x; i < n_blocks;
         i += gridDim.x * blockDim.x)
        g_sums[i] = make_float4(0.f, 0.f, 0.f, 0.f);
}

// One atom per lane (coalesced). Warp-level segmented reduction over the
// sorted block ids; only segment heads issue atomics.  (Known-good flat
// version: ~15us.)
__global__ void k_accum(const float* __restrict__ pos,
                        const int* __restrict__ bid,
                        int n_atoms) {
    int i    = blockIdx.x * blockDim.x + threadIdx.x;
    int lane = threadIdx.x & 31;

    bool valid = i < n_atoms;
    int idx = valid ? i : (n_atoms - 1);

    int   b   = bid[idx];
    float sx  = valid ? pos[3 * idx + 0] : 0.f;
    float sy  = valid ? pos[3 * idx + 1] : 0.f;
    float sz  = valid ? pos[3 * idx + 2] : 0.f;
    float cnt = valid ? 1.f : 0.f;

#pragma unroll
    for (int off = 1; off < 32; off <<= 1) {
        int   ob = __shfl_down_sync(0xffffffffu, b, off);
        float ox = __shfl_down_sync(0xffffffffu, sx, off);
        float oy = __shfl_down_sync(0xffffffffu, sy, off);
        float oz = __shfl_down_sync(0xffffffffu, sz, off);
        float oc = __shfl_down_sync(0xffffffffu, cnt, off);
        if (lane + off < 32 && ob == b) {
            sx += ox; sy += oy; sz += oz; cnt += oc;
        }
    }

    int prev_b = __shfl_up_sync(0xffffffffu, b, 1);
    bool head = (lane == 0) || (prev_b != b);
    if (head && cnt > 0.f) {
        float* p = (float*)&g_sums[b];
        atomicAdd(p + 0, sx);
        atomicAdd(p + 1, sy);
        atomicAdd(p + 2, sz);
        atomicAdd(p + 3, cnt);
    }
}

__global__ void k_centroid(float* __restrict__ out_c, int n_blocks) {
    for (int i = blockIdx.x * blockDim.x + threadIdx.x; i < n_blocks;
         i += gridDim.x * blockDim.x) {
        float4 s = g_sums[i];
        float inv = 1.f / fmaxf(s.w, 1.f);
        out_c[3 * i + 0] = s.x * inv;
        out_c[3 * i + 1] = s.y * inv;
        out_c[3 * i + 2] = s.z * inv;
    }
}

// Per-atom kernel with TRANSPOSED rbf stores.
//  - pos staged cooperatively as float4 into shared (3 wf/warp vs 9 scalar)
//  - rel computed per-atom, written back to shared, stored coop as float4
//  - dist stored per-atom (1 wf/warp)
//  - rbf: 4 rounds per warp; round r: lane L handles atom (w0+8r+L/4),
//    k-quarter q=L%4 -> one STG.128 whose 32 lanes cover 512 contiguous
//    bytes (4 wavefronts/instr instead of 16). d redistributed via shfl.
//    Each lane's 4 (center, inv2w2) pairs live in registers.
__global__ void __launch_bounds__(TPB, 6)
k_atoms(const float* __restrict__ pos,
        const int* __restrict__ bid,
        const float* __restrict__ centers,
        const float* __restrict__ widths,
        float* __restrict__ out_rel,
        float* __restrict__ out_dist,
        float4* __restrict__ out_rbf,     // n_atoms * 4 float4
        int n_atoms) {
    __shared__ float s_c[RBF_DIM];
    __shared__ float s_iw[RBF_DIM];
    __shared__ float s_xyz[3 * TPB];      // staged pos, then reused for rel

    int t    = threadIdx.x;
    int lane = t & 31;

    if (t < RBF_DIM) {
        s_c[t] = centers[t];
        float w = widths[t];
        s_iw[t] = 1.f / (2.f * w * w);
    }

    int a0 = blockIdx.x * TPB;            // first atom of this block
    bool fullt = (a0 + TPB) <= n_atoms;

    // ---- stage pos into shared ----
    if (fullt) {
        const float4* p4 = (const float4*)(pos + (size_t)3 * a0);
        if (t < (3 * TPB / 4)) ((float4*)s_xyz)[t] = p4[t];
    } else {
        for (int k = t; k < 3 * TPB; k += TPB) {
            int gi = 3 * a0 + k;
            s_xyz[k] = (gi < 3 * n_atoms) ? pos[gi] : 0.f;
        }
    }
    __syncthreads();

    // per-lane RBF constants (q = lane & 3 fixed for this thread)
    int q = lane & 3;
    float c0 = s_c[4 * q + 0], c1 = s_c[4 * q + 1];
    float c2 = s_c[4 * q + 2], c3 = s_c[4 * q + 3];
    float w0 = s_iw[4 * q + 0], w1 = s_iw[4 * q + 1];
    float w2 = s_iw[4 * q + 2], w3 = s_iw[4 * q + 3];

    int i = a0 + t;
    bool act = i < n_atoms;
    float d = 0.f;

    if (act) {
        int b = bid[i];
        float4 s = g_sums[b];             // single LDG.128, broadcast-friendly
        float inv = 1.f / fmaxf(s.w, 1.f);

        float rx = s_xyz[3 * t + 0] - s.x * inv;
        float ry = s_xyz[3 * t + 1] - s.y * inv;
        float rz = s_xyz[3 * t + 2] - s.z * inv;

        s_xyz[3 * t + 0] = rx;            // self-overwrite, no hazard
        s_xyz[3 * t + 1] = ry;
        s_xyz[3 * t + 2] = rz;

        d = sqrtf(rx * rx + ry * ry + rz * rz);
        __stcs(&out_dist[i], d);
    }
    __syncthreads();

    // ---- cooperative rel store ----
    if (fullt) {
        float4* r4 = (float4*)(out_rel + (size_t)3 * a0);
        if (t < (3 * TPB / 4)) __stcs(&r4[t], ((const float4*)s_xyz)[t]);
    } else {
        for (int k = t; k < 3 * TPB; k += TPB) {
            int gi = 3 * a0 + k;
            if (gi < 3 * n_atoms) out_rel[gi] = s_xyz[k];
        }
    }

    // ---- transposed rbf stores ----
    // warp's atom base:
    int wbase = a0 + (t & ~31);
    int sub   = lane >> 2;                // 0..7: which atom within the round's 8
#pragma unroll
    for (int r = 0; r < 4; ++r) {
        int src_lane = 8 * r + sub;       // lane holding this atom's d
        float dd = __shfl_sync(0xffffffffu, d, src_lane);
        int atom = wbase + 8 * r + sub;
        if (atom < n_atoms) {
            float u;
            float4 v;
            u = dd - c0; v.x = __expf(-u * u * w0);
            u = dd - c1; v.y = __expf(-u * u * w1);
            u = dd - c2; v.z = __expf(-u * u * w2);
            u = dd - c3; v.w = __expf(-u * u * w3);
            // float4 index: atom*4 + q -> lanes cover 32 consecutive float4
            __stcs(&out_rbf[(size_t)atom * 4 + q], v);
        }
    }
}

static inline int clamp_grid(long long b) {
    if (b < 1) return 1;
    if (b > 1048576) return 1048576;
    return (int)b;
}

extern "C" void kernel_launch(void* const* d_in, const int* in_sizes, int n_in,
                              void* d_out, int out_size) {
    const float* pos     = (const float*)d_in[0];  // [n_atoms*3]
    const int*   bid     = (const int*)d_in[1];    // [n_atoms]
    // d_in[2] = n_blocks scalar on device; derive arithmetically (no sync copies)
    const float* centers = (const float*)d_in[3];  // [16]
    const float* widths  = (const float*)d_in[4];  // [16]

    int n_atoms  = in_sizes[0] / 3;
    long long nb = ((long long)out_size - (long long)n_atoms * (3 + 1 + RBF_DIM)) / 3;
    int n_blocks = (int)nb;
    if (n_blocks < 1) n_blocks = 1;
    if (n_blocks > MAX_BLOCKS_SCRATCH) n_blocks = MAX_BLOCKS_SCRATCH;

    float* out      = (float*)d_out;
    float* out_cent = out;                                    // n_blocks*3
    float* out_rel  = out + (size_t)n_blocks * 3;             // n_atoms*3
    float* out_dist = out_rel + (size_t)n_atoms * 3;          // n_atoms
    float4* out_rbf = (float4*)(out_dist + (size_t)n_atoms);  // n_atoms*16 floats

    // 1) zero scratch
    k_zero_sums<<<clamp_grid((n_blocks + 255) / 256), 256>>>(n_blocks);

    // 2) segment sums (flat, coalesced, warp-aggregated atomics)
    if (n_atoms > 0)
        k_accum<<<clamp_grid(((long long)n_atoms + 255) / 256), 256>>>(pos, bid, n_atoms);

    // 3) centroids output
    k_centroid<<<clamp_grid((n_blocks + 255) / 256), 256>>>(out_cent, n_blocks);

    // 4) per-atom rel/dist/rbf (flat grid; reads g_sums directly)
    if (n_atoms > 0)
        k_atoms<<<clamp_grid(((long long)n_atoms + TPB - 1) / TPB), TPB>>>(
            pos, bid, centers, widths, out_rel, out_dist, out_rbf, n_atoms);
}